// round 15
// baseline (speedup 1.0000x reference)
#include <cuda_runtime.h>

// QORNN: B=256, T=1024, I=64, H=256, O=16
// Exact integer formulation (bit-exact vs the JAX fp32 reference):
//   xq  = clip(rint(x*128), -128, 127)              (int8)
//   wiq = clip(rint(Wi*8),  -8, 7)
//   wrq = clip(rint(Wr*8),  -8, 7)
//   woq = clip(rint(Wo*8),  -8, 7)
//   z_int = sum_i xq*wiq + sum_k hq*wrq             (|.| <= 327680 < 2^24)
//   m  = min(max(fma(|z|, 1/8, 128*b[j]), 0), 128)  (== 128*ref-m; az*0.125
//                                                    exact, single rounding)
//   hq = (z==0) ? 0 : min(rint(copysign(m,z)), 127) in [-128,127]
//        (rint half-even is symmetric -> == sign(z)*clip(rint(m)) of the ref)
//   out[b,o] = (sum_j hq*woq) / 1024
//
// Layout: one CTA (256 threads) per batch row, thread j owns column j; Wr
// row j (64 regs) + Wi row j (16 regs) in registers; h double-buffered in
// smem; x loaded 8 steps ahead into a smem ring. Per-step order is the R7
// schedule (measured best):
//   h-dot -> x-pipeline -> u(t+1)-dot -> epilogue -> STS(h) -> BAR
// The independent u-dot instructions interleave with the h-dot add-tree and
// the serial modReLU chain, keeping each warp issuable (R9's
// epilogue-first reorder removed that overlap and regressed).
// x-pipeline ownership is spread across all 8 warps (lanes 0-7 each) so
// every warp carries equal per-step work and barrier arrivals stay tight.

#define BB 256
#define TT 1024
#define II 64
#define HH 256
#define OO 16

// Packed quantized weights (allocation-free rule: __device__ globals)
__device__ int d_wr4[64 * HH];      // [q][j]: packed wrq[j][4q..4q+3]
__device__ int d_wi4[16 * HH];      // [q][j]: packed wiq[j][4q..4q+3]
__device__ int d_wo4[OO * 64];      // [o][q]: packed woq[o][4q..4q+3]

__device__ __forceinline__ int clampi(int v, int lo, int hi) {
    return v < lo ? lo : (v > hi ? hi : v);
}

// Quantize 4 floats (round-half-even, clip) and pack into one dp4a word.
__device__ __forceinline__ int qpack4(float4 v, float s, int lo, int hi) {
    int a = clampi(__float2int_rn(v.x * s), lo, hi);
    int b = clampi(__float2int_rn(v.y * s), lo, hi);
    int c = clampi(__float2int_rn(v.z * s), lo, hi);
    int d = clampi(__float2int_rn(v.w * s), lo, hi);
    return (a & 255) | ((b & 255) << 8) | ((c & 255) << 16) | ((d & 255) << 24);
}

// ---------------------------------------------------------------------------
// Kernel 1: quantize + pack all weights. 256 CTAs x 64 threads.
// ---------------------------------------------------------------------------
__global__ void __launch_bounds__(64) pack_weights_kernel(
        const float* __restrict__ Wi,
        const float* __restrict__ Wr,
        const float* __restrict__ Wo) {
    int j = blockIdx.x;   // 0..255
    int q = threadIdx.x;  // 0..63

    const float4* wr = (const float4*)(Wr + j * HH);
    d_wr4[q * HH + j] = qpack4(wr[q], 8.0f, -8, 7);

    if (q < 16) {
        const float4* wi = (const float4*)(Wi + j * II);
        d_wi4[q * HH + j] = qpack4(wi[q], 8.0f, -8, 7);
    }
    if (j < OO) {
        const float4* wo = (const float4*)(Wo + j * HH);
        d_wo4[j * 64 + q] = qpack4(wo[q], 8.0f, -8, 7);
    }
}

// ---------------------------------------------------------------------------
// Kernel 2: fused projection + recurrence + output head.
// ---------------------------------------------------------------------------
__global__ void __launch_bounds__(256, 2)
rnn_kernel(const float* __restrict__ X, const float* __restrict__ bvec,
           float* __restrict__ out) {
    __shared__ int4 hs[2][16];    // two 256-byte h buffers
    __shared__ int4 xring[8][4];  // 8-step ring of packed xq (64 bytes/slot)
    __shared__ int  stagger_sink;

    int b = blockIdx.x;
    int j = threadIdx.x;

    int w[64];
#pragma unroll
    for (int q = 0; q < 64; q++) w[q] = d_wr4[q * HH + j];
    int wi[16];
#pragma unroll
    for (int q = 0; q < 16; q++) wi[q] = d_wi4[q * HH + j];

    float bj128 = bvec[j] * 128.0f;  // exact (|b|~0.03, power-of-2 scale)

    if (j < 32) ((int4*)hs)[j] = make_int4(0, 0, 0, 0);  // h0 = 0, both bufs

    // x pipeline ownership spread across warps: lanes 0-7 of warp wid own
    // x columns xc = wid*8 + lane (64 columns total, 8 per warp).
    int lane = j & 31, wid = j >> 5;
    bool xown = lane < 8;
    int  xc   = wid * 8 + lane;
    const float* xp = X + (size_t)b * TT * II + xc;
    float rcur = 0.0f;
    if (xown) {
        signed char* ring = (signed char*)xring;
#pragma unroll
        for (int p = 0; p < 7; p++) {
            int v = clampi(__float2int_rn(xp[p * II] * 128.0f), -128, 127);
            ring[p * 64 + xc] = (signed char)v;
        }
        rcur = xp[7 * II];
    }

    if (b >= 148) {
        // ~400-cycle dependent-IMAD delay: anti-phase vs co-resident CTA so
        // the two CTAs' epilogue/barrier tails interleave with dp4a bursts.
        int x = j | 1;
#pragma unroll 1
        for (int i = 0; i < 96; i++) x = x * x + j;
        if (x == 13) stagger_sink = x;  // keep chain alive; never read
    }
    __syncthreads();

    // u(0) = xq(0) . wi_row(j)
    int uacc;
    {
        const int4* xw = xring[0];
        int c0 = 0, c1 = 0, c2 = 0, c3 = 0;
#pragma unroll
        for (int g = 0; g < 4; g++) {
            int4 xv = xw[g];
            c0 = __dp4a(xv.x, wi[4 * g + 0], c0);
            c1 = __dp4a(xv.y, wi[4 * g + 1], c1);
            c2 = __dp4a(xv.z, wi[4 * g + 2], c2);
            c3 = __dp4a(xv.w, wi[4 * g + 3], c3);
        }
        uacc = (c0 + c1) + (c2 + c3);
    }

#pragma unroll 1
    for (int tb = 0; tb < TT; tb += 8) {
#pragma unroll
        for (int uu = 0; uu < 8; uu++) {
            int t = tb + uu;

            // ---- h-dot for step t: 64 dp4a, 8 independent chains; uacc
            //      seeds chain a0 (removes one dependent add from z) ----
            const int4* hp = hs[uu & 1];
            int a0 = uacc, a1 = 0, a2 = 0, a3 = 0,
                a4 = 0,    a5 = 0, a6 = 0, a7 = 0;
#pragma unroll
            for (int g = 0; g < 8; g++) {
                int4 h0 = hp[2 * g + 0];
                int4 h1 = hp[2 * g + 1];
                a0 = __dp4a(h0.x, w[8 * g + 0], a0);
                a1 = __dp4a(h0.y, w[8 * g + 1], a1);
                a2 = __dp4a(h0.z, w[8 * g + 2], a2);
                a3 = __dp4a(h0.w, w[8 * g + 3], a3);
                a4 = __dp4a(h1.x, w[8 * g + 4], a4);
                a5 = __dp4a(h1.y, w[8 * g + 5], a5);
                a6 = __dp4a(h1.z, w[8 * g + 6], a6);
                a7 = __dp4a(h1.w, w[8 * g + 7], a7);
            }
            int z = (((a0 + a1) + (a2 + a3)) + ((a4 + a5) + (a6 + a7)));

            // ---- x pipeline (h-independent; interleaves with h-dot tail
            //      and the epilogue's serial chain) ----
            if (xown) {
                int tn = t + 8;
                if (tn > TT - 1) tn = TT - 1;
                float rnext = xp[tn * II];
                int v = clampi(__float2int_rn(rcur * 128.0f), -128, 127);
                ((signed char*)xring[(uu + 7) & 7])[xc] = (signed char)v;
                rcur = rnext;
            }
            // u(t+1) from ring slot (t+1)&7 (written >= 6 barriers ago).
            {
                const int4* xw = xring[(uu + 1) & 7];
                int c0 = 0, c1 = 0, c2 = 0, c3 = 0;
#pragma unroll
                for (int g = 0; g < 4; g++) {
                    int4 xv = xw[g];
                    c0 = __dp4a(xv.x, wi[4 * g + 0], c0);
                    c1 = __dp4a(xv.y, wi[4 * g + 1], c1);
                    c2 = __dp4a(xv.z, wi[4 * g + 2], c2);
                    c3 = __dp4a(xv.w, wi[4 * g + 3], c3);
                }
                uacc = (c0 + c1) + (c2 + c3);
            }

            // ---- modReLU + 8-bit requantization (bit-exact) ----
            int az = z < 0 ? -z : z;
            float m = fminf(fmaxf(fmaf((float)az, 0.125f, bj128), 0.0f),
                            128.0f);
            // copysign(m, z) via sign-bit OR (one LOP3); half-even rint is
            // symmetric, so this equals sign(z)*rint(m).
            float ms = __int_as_float(__float_as_int(m) |
                                      (int)((unsigned)z & 0x80000000u));
            int r = __float2int_rn(ms);
            int rp = r < 127 ? r : 127;      // positive cap (neg side >= -128)
            int hq = (z == 0) ? 0 : rp;

            ((signed char*)hs[(uu + 1) & 1])[j] = (signed char)hq;
            __syncthreads();
        }
    }

    // Output head: out[b,o] = (h_last . woq_row(o)) / 1024. Final h in hs[0]
    // (T even: last step wrote buffer (uu+1)&1 == 0).
    if (j < OO) {
        const int* hw = (const int*)hs[0];
        int acc = 0;
#pragma unroll
        for (int g = 0; g < 64; g++) acc = __dp4a(hw[g], d_wo4[j * 64 + g], acc);
        out[b * OO + j] = (float)acc * (1.0f / 1024.0f);
    }
}

// ---------------------------------------------------------------------------
extern "C" void kernel_launch(void* const* d_in, const int* in_sizes, int n_in,
                              void* d_out, int out_size) {
    const float* X  = (const float*)d_in[0];  // inputs [256,1024,64]
    const float* Wi = (const float*)d_in[1];  // [256,64]
    const float* Wr = (const float*)d_in[2];  // [256,256]
    const float* Wo = (const float*)d_in[3];  // [16,256]
    const float* bv = (const float*)d_in[4];  // [256]

    pack_weights_kernel<<<256, 64>>>(Wi, Wr, Wo);
    rnn_kernel<<<BB, 256>>>(X, bv, (float*)d_out);
}

// round 16
// speedup vs baseline: 1.1323x; 1.1323x over previous
#include <cuda_runtime.h>

// QORNN: B=256, T=1024, I=64, H=256, O=16
// Exact integer formulation (bit-exact vs the JAX fp32 reference):
//   xq  = clip(rint(x*128), -128, 127)              (int8)
//   wiq = clip(rint(Wi*8),  -8, 7)
//   wrq = clip(rint(Wr*8),  -8, 7)
//   woq = clip(rint(Wo*8),  -8, 7)
//   z_int = sum_i xq*wiq + sum_k hq*wrq             (|.| <= 327680 < 2^24)
//   m  = max(fma(|z|, 1/8, 128*b[j]), 0)            (== 128*ref-m; exact
//                                                    pow2 scaling, single
//                                                    fp32 rounding == ref)
//   hq = sign(z)*clip(rint(m), ..)                  in [-128,127]
//   out[b,o] = (sum_j hq*woq) / 1024
//
// This is the measured-best R7 structure restored verbatim (one CTA of 256
// threads per batch row; thread j owns column j with Wr row j in 64 regs and
// Wi row j in 16 regs; h double-buffered in smem; x loaded 8 steps ahead
// into a smem ring; per-step order h-dot -> x-pipeline -> u(t+1)-dot ->
// epilogue -> STS -> BAR, which interleaves the h-independent u-dot into the
// warp's dependency gaps). Single delta vs R7: the x-pipeline is owned by
// warps 6-7 (j >= 192) instead of warps 0-1 — the arbiter is hi-wid-first,
// so the x-warps' extra ~25 instrs/step issue at top priority and their
// barrier arrival no longer trails the pack. Spreading this work across all
// warps (R14) or reordering the epilogue (R9/R13) both measured worse; the
// concentration quarantines the LDG long-scoreboard dependency to 2 warps.

#define BB 256
#define TT 1024
#define II 64
#define HH 256
#define OO 16

// Packed quantized weights (allocation-free rule: __device__ globals)
__device__ int d_wr4[64 * HH];      // [q][j]: packed wrq[j][4q..4q+3]
__device__ int d_wi4[16 * HH];      // [q][j]: packed wiq[j][4q..4q+3]
__device__ int d_wo4[OO * 64];      // [o][q]: packed woq[o][4q..4q+3]

__device__ __forceinline__ int clampi(int v, int lo, int hi) {
    return v < lo ? lo : (v > hi ? hi : v);
}

// Quantize 4 floats (round-half-even, clip) and pack into one dp4a word.
__device__ __forceinline__ int qpack4(float4 v, float s, int lo, int hi) {
    int a = clampi(__float2int_rn(v.x * s), lo, hi);
    int b = clampi(__float2int_rn(v.y * s), lo, hi);
    int c = clampi(__float2int_rn(v.z * s), lo, hi);
    int d = clampi(__float2int_rn(v.w * s), lo, hi);
    return (a & 255) | ((b & 255) << 8) | ((c & 255) << 16) | ((d & 255) << 24);
}

// ---------------------------------------------------------------------------
// Kernel 1: quantize + pack all weights. 256 CTAs x 64 threads.
// ---------------------------------------------------------------------------
__global__ void __launch_bounds__(64) pack_weights_kernel(
        const float* __restrict__ Wi,
        const float* __restrict__ Wr,
        const float* __restrict__ Wo) {
    int j = blockIdx.x;   // 0..255
    int q = threadIdx.x;  // 0..63

    const float4* wr = (const float4*)(Wr + j * HH);
    d_wr4[q * HH + j] = qpack4(wr[q], 8.0f, -8, 7);

    if (q < 16) {
        const float4* wi = (const float4*)(Wi + j * II);
        d_wi4[q * HH + j] = qpack4(wi[q], 8.0f, -8, 7);
    }
    if (j < OO) {
        const float4* wo = (const float4*)(Wo + j * HH);
        d_wo4[j * 64 + q] = qpack4(wo[q], 8.0f, -8, 7);
    }
}

// ---------------------------------------------------------------------------
// Kernel 2: fused projection + recurrence + output head.
// ---------------------------------------------------------------------------
__global__ void __launch_bounds__(256, 2)
rnn_kernel(const float* __restrict__ X, const float* __restrict__ bvec,
           float* __restrict__ out) {
    __shared__ int4 hs[2][16];    // two 256-byte h buffers
    __shared__ int4 xring[8][4];  // 8-step ring of packed xq (64 bytes/slot)
    __shared__ int  stagger_sink;

    int b = blockIdx.x;
    int j = threadIdx.x;

    int w[64];
#pragma unroll
    for (int q = 0; q < 64; q++) w[q] = d_wr4[q * HH + j];
    int wi[16];
#pragma unroll
    for (int q = 0; q < 16; q++) wi[q] = d_wi4[q * HH + j];

    float bj128 = bvec[j] * 128.0f;  // exact (|b|~0.03, power-of-2 scale)

    if (j < 32) ((int4*)hs)[j] = make_int4(0, 0, 0, 0);  // h0 = 0, both bufs

    // x pipeline owned by warps 6-7 (hi-wid arbiter priority): thread j in
    // [192,256) owns x column xc = j-192.
    bool xown = j >= 192;
    int  xc   = j - 192;
    const float* xp = X + (size_t)b * TT * II + xc;
    float rcur = 0.0f;
    if (xown) {
        signed char* ring = (signed char*)xring;
#pragma unroll
        for (int p = 0; p < 7; p++) {
            int v = clampi(__float2int_rn(xp[p * II] * 128.0f), -128, 127);
            ring[p * 64 + xc] = (signed char)v;
        }
        rcur = xp[7 * II];
    }

    if (b >= 148) {
        // ~400-cycle dependent-IMAD delay: anti-phase vs co-resident CTA so
        // the two CTAs' epilogue/barrier tails interleave with dp4a bursts.
        int x = j | 1;
#pragma unroll 1
        for (int i = 0; i < 96; i++) x = x * x + j;
        if (x == 13) stagger_sink = x;  // keep chain alive; never read
    }
    __syncthreads();

    // u(0) = xq(0) . wi_row(j)
    int uacc;
    {
        const int4* xw = xring[0];
        int c0 = 0, c1 = 0, c2 = 0, c3 = 0;
#pragma unroll
        for (int g = 0; g < 4; g++) {
            int4 xv = xw[g];
            c0 = __dp4a(xv.x, wi[4 * g + 0], c0);
            c1 = __dp4a(xv.y, wi[4 * g + 1], c1);
            c2 = __dp4a(xv.z, wi[4 * g + 2], c2);
            c3 = __dp4a(xv.w, wi[4 * g + 3], c3);
        }
        uacc = (c0 + c1) + (c2 + c3);
    }

#pragma unroll 1
    for (int tb = 0; tb < TT; tb += 8) {
#pragma unroll
        for (int uu = 0; uu < 8; uu++) {
            int t = tb + uu;

            // ---- h-dot for step t: 64 dp4a, 8 independent chains ----
            const int4* hp = hs[uu & 1];
            int a0 = 0, a1 = 0, a2 = 0, a3 = 0, a4 = 0, a5 = 0, a6 = 0, a7 = 0;
#pragma unroll
            for (int g = 0; g < 8; g++) {
                int4 h0 = hp[2 * g + 0];
                int4 h1 = hp[2 * g + 1];
                a0 = __dp4a(h0.x, w[8 * g + 0], a0);
                a1 = __dp4a(h0.y, w[8 * g + 1], a1);
                a2 = __dp4a(h0.z, w[8 * g + 2], a2);
                a3 = __dp4a(h0.w, w[8 * g + 3], a3);
                a4 = __dp4a(h1.x, w[8 * g + 4], a4);
                a5 = __dp4a(h1.y, w[8 * g + 5], a5);
                a6 = __dp4a(h1.z, w[8 * g + 6], a6);
                a7 = __dp4a(h1.w, w[8 * g + 7], a7);
            }
            int z = uacc +
                    ((((a0 + a1) + (a2 + a3)) + ((a4 + a5) + (a6 + a7))));

            // ---- x pipeline (h-independent; fills the epilogue window) ----
            // quantize x(t+7) (loaded last step) into ring slot (t+7)&7,
            // issue load of x(t+8).
            if (xown) {
                int tn = t + 8;
                if (tn > TT - 1) tn = TT - 1;
                float rnext = xp[tn * II];
                int v = clampi(__float2int_rn(rcur * 128.0f), -128, 127);
                ((signed char*)xring[(uu + 7) & 7])[xc] = (signed char)v;
                rcur = rnext;
            }
            // u(t+1) from ring slot (t+1)&7 (written >= 6 barriers ago).
            {
                const int4* xw = xring[(uu + 1) & 7];
                int c0 = 0, c1 = 0, c2 = 0, c3 = 0;
#pragma unroll
                for (int g = 0; g < 4; g++) {
                    int4 xv = xw[g];
                    c0 = __dp4a(xv.x, wi[4 * g + 0], c0);
                    c1 = __dp4a(xv.y, wi[4 * g + 1], c1);
                    c2 = __dp4a(xv.z, wi[4 * g + 2], c2);
                    c3 = __dp4a(xv.w, wi[4 * g + 3], c3);
                }
                uacc = (c0 + c1) + (c2 + c3);
            }

            // ---- modReLU + 8-bit requantization (bit-exact) ----
            int az = z < 0 ? -z : z;
            float m = fmaxf(fmaf((float)az, 0.125f, bj128), 0.0f);
            m = fminf(m, 128.0f);            // negative-side cap; fma pipe
            int r = __float2int_rn(m);       // r >= 0, half-even
            int rp = r < 127 ? r : 127;      // positive-side cap
            int hq = (z > 0) ? rp : (z < 0 ? -r : 0);

            ((signed char*)hs[(uu + 1) & 1])[j] = (signed char)hq;
            __syncthreads();
        }
    }

    // Output head: out[b,o] = (h_last . woq_row(o)) / 1024. Final h in hs[0]
    // (T even: last step wrote buffer (uu+1)&1 == 0).
    if (j < OO) {
        const int* hw = (const int*)hs[0];
        int acc = 0;
#pragma unroll
        for (int g = 0; g < 64; g++) acc = __dp4a(hw[g], d_wo4[j * 64 + g], acc);
        out[b * OO + j] = (float)acc * (1.0f / 1024.0f);
    }
}

// ---------------------------------------------------------------------------
extern "C" void kernel_launch(void* const* d_in, const int* in_sizes, int n_in,
                              void* d_out, int out_size) {
    const float* X  = (const float*)d_in[0];  // inputs [256,1024,64]
    const float* Wi = (const float*)d_in[1];  // [256,64]
    const float* Wr = (const float*)d_in[2];  // [256,256]
    const float* Wo = (const float*)d_in[3];  // [16,256]
    const float* bv = (const float*)d_in[4];  // [256]

    pack_weights_kernel<<<256, 64>>>(Wi, Wr, Wo);
    rnn_kernel<<<BB, 256>>>(X, bv, (float*)d_out);
}